// round 12
// baseline (speedup 1.0000x reference)
#include <cuda_runtime.h>
#include <cuda_fp16.h>
#include <cstdint>

// ---------------- problem constants ----------------
constexpr int BATCH = 8192;
constexpr int DH    = 1024;

// ---------------- tiling ----------------
constexpr int BM      = 128;   // batch rows per CTA
constexpr int BNG     = 32;    // cols per gate per CTA
constexpr int NTOT    = 128;   // 4 gates x 32
constexpr int BK      = 64;    // K halfs per chunk
constexpr int KITERS  = 32;    // 2048 / 64
constexpr int NSTAGES = 4;     // B-only stages
constexpr int THREADS = 256;   // 8 warps: 4(M) x 2(N)

constexpr int B_STAGE_BYTES = NTOT * 128;                 // 16384 (B only)
constexpr int MBAR_OFF      = NSTAGES * B_STAGE_BYTES;    // 65536
constexpr int CNT_OFF       = MBAR_OFF + 32;
constexpr int SMEM_BYTES    = MBAR_OFF + 128;             // 65664 -> 2 CTAs/SM

// ---------------- scratch ----------------
// A: fragment-ordered: [bt(64)][chunk(32)][wm(4)][mt(2)][kk(4)][lane(32)] x 16B
//    16B = {a0,a1,a2,a3} of one thread's m16n8k16 A-fragment. (chunks 0-15: x, 16-31: h)
// B: row layout for ldsm: [jt(32)][chunk(32)][row(g*32+jl)(128)][64 halfs, XOR-swizzled]
__device__ __align__(128) __half g_sA[64u * 32u * 8192u];   // 32 MB
__device__ __align__(128) __half g_sB[32u * 32u * 8192u];   // 16 MB

template <int N> struct IC { static constexpr int value = N; };

struct Params {
    const float* x;
    const float* h;
    const float* c;
    const float* W[4];
    const float* U[4];
    const float* bias[4];
    float* outh;
    float* outc;
};

// ---------------- helpers ----------------
__device__ __forceinline__ uint32_t smem_u32(const void* p) {
    uint32_t a;
    asm("{ .reg .u64 t; cvta.to.shared.u64 t, %1; cvt.u32.u64 %0, t; }" : "=r"(a) : "l"(p));
    return a;
}
__device__ __forceinline__ void mbar_init(uint32_t a, uint32_t cnt) {
    asm volatile("mbarrier.init.shared.b64 [%0], %1;" :: "r"(a), "r"(cnt) : "memory");
}
__device__ __forceinline__ void mbar_expect_tx(uint32_t a, uint32_t tx) {
    asm volatile("mbarrier.arrive.expect_tx.shared.b64 _, [%0], %1;" :: "r"(a), "r"(tx) : "memory");
}
__device__ __forceinline__ void mbar_wait(uint32_t a, uint32_t parity) {
    asm volatile(
        "{\n\t.reg .pred P;\n"
        "W%=:\n\t"
        "mbarrier.try_wait.parity.shared::cta.b64 P, [%0], %1, 0x989680;\n\t"
        "@!P bra W%=;\n\t}"
        :: "r"(a), "r"(parity) : "memory");
}
__device__ __forceinline__ void bulk_g2s(uint32_t dst, const void* src, uint32_t bytes, uint32_t mbar) {
    asm volatile(
        "cp.async.bulk.shared::cluster.global.mbarrier::complete_tx::bytes [%0], [%1], %2, [%3];"
        :: "r"(dst), "l"(src), "r"(bytes), "r"(mbar) : "memory");
}
__device__ __forceinline__ void ldsm_x4(uint32_t* r, uint32_t addr) {
    asm volatile("ldmatrix.sync.aligned.m8n8.x4.shared.b16 {%0,%1,%2,%3}, [%4];"
        : "=r"(r[0]), "=r"(r[1]), "=r"(r[2]), "=r"(r[3]) : "r"(addr));
}
__device__ __forceinline__ void mma_f16(float* d, const uint32_t* a, const uint32_t* b) {
    asm volatile(
        "mma.sync.aligned.m16n8k16.row.col.f32.f16.f16.f32 "
        "{%0,%1,%2,%3}, {%4,%5,%6,%7}, {%8,%9}, {%0,%1,%2,%3};"
        : "+f"(d[0]), "+f"(d[1]), "+f"(d[2]), "+f"(d[3])
        : "r"(a[0]), "r"(a[1]), "r"(a[2]), "r"(a[3]), "r"(b[0]), "r"(b[1]));
}
__device__ __forceinline__ float sigm(float v) {
    return __fdividef(1.0f, 1.0f + __expf(-v));
}
__device__ __forceinline__ float ftanh(float v) {
    return __fmaf_rn(2.0f, sigm(2.0f * v), -1.0f);
}

// ---------------- pass 1: fp32 -> fp16 (A: fragment order, B: ldsm rows) ----------------
// Grid: blocks 0..2047  : A, one (bt, chunk) 128x64 tile per block (smem transpose)
//       blocks 2048..3071: B, elementwise (1024 16B items per block)
constexpr int A_BLOCKS = 64 * 32;        // 2048
constexpr int B_BLOCKS = 1024;
constexpr int CVT_SMEM_PAD = 66;         // floats per row (pad vs bank conflicts)

__global__ void __launch_bounds__(256) convert_kernel(Params p)
{
    const int tid = threadIdx.x;

    if (blockIdx.x < A_BLOCKS) {
        __shared__ float sa[128 * CVT_SMEM_PAD];
        const int bt = blockIdx.x >> 5;
        const int kc = blockIdx.x & 31;
        const float* src = (kc < 16 ? p.x : p.h)
                           + (size_t)(bt * 128) * 1024 + (kc & 15) * 64;
        // load 128 rows x 64 floats, coalesced (16 float4 per row)
        #pragma unroll
        for (int i = 0; i < 8; i++) {
            const int fidx = tid + i * 256;          // 0..2047
            const int r = fidx >> 4, c4 = fidx & 15;
            const float4 v = *(const float4*)(src + (size_t)r * 1024 + c4 * 4);
            float* d = sa + r * CVT_SMEM_PAD + c4 * 4;
            d[0] = v.x; d[1] = v.y; d[2] = v.z; d[3] = v.w;
        }
        __syncthreads();
        // write 1024 fragment items (16B each), coalesced
        __half* dstT = g_sA + ((size_t)bt * 32 + kc) * 8192u;
        #pragma unroll
        for (int i = 0; i < 4; i++) {
            const int item = tid + i * 256;          // 0..1023
            const int lane = item & 31;
            const int kk   = (item >> 5) & 3;
            const int mt   = (item >> 7) & 1;
            const int wm   = item >> 8;
            const int r0 = wm * 32 + mt * 16 + (lane >> 2);
            const int c0 = kk * 16 + (lane & 3) * 2;
            const float* s0 = sa + r0 * CVT_SMEM_PAD + c0;
            const float* s1 = sa + (r0 + 8) * CVT_SMEM_PAD + c0;
            __half2 a0 = __floats2half2_rn(s0[0], s0[1]);
            __half2 a1 = __floats2half2_rn(s1[0], s1[1]);
            __half2 a2 = __floats2half2_rn(s0[8], s0[9]);
            __half2 a3 = __floats2half2_rn(s1[8], s1[9]);
            uint4 pk;
            pk.x = *(const uint32_t*)&a0;
            pk.y = *(const uint32_t*)&a1;
            pk.z = *(const uint32_t*)&a2;
            pk.w = *(const uint32_t*)&a3;
            *(uint4*)(dstT + (size_t)item * 8) = pk;
        }
    } else {
        // B: same mapping as prior rounds
        #pragma unroll
        for (int i = 0; i < 4; i++) {
            const int t = (blockIdx.x - A_BLOCKS) * 1024 + i * 256 + tid;
            const int c16 = t & 7;
            const int r   = (t >> 3) & 127;          // g*32 + jl
            const int kc  = (t >> 10) & 31;
            const int jt  = t >> 15;
            const int g   = r >> 5, jl = r & 31;
            const float* src = (kc < 16 ? p.W[g] : p.U[g])
                  + (size_t)(jt * 32 + jl) * 1024 + (kc & 15) * 64 + c16 * 8;
            __half* dst = g_sB + ((size_t)(jt * 32 + kc) * 128 + r) * 64 + ((c16 ^ (r & 7)) * 8);
            const float4 v0 = *(const float4*)(src);
            const float4 v1 = *(const float4*)(src + 4);
            __half2 h0 = __floats2half2_rn(v0.x, v0.y);
            __half2 h1 = __floats2half2_rn(v0.z, v0.w);
            __half2 h2 = __floats2half2_rn(v1.x, v1.y);
            __half2 h3 = __floats2half2_rn(v1.z, v1.w);
            uint4 pk;
            pk.x = *(const uint32_t*)&h0;
            pk.y = *(const uint32_t*)&h1;
            pk.z = *(const uint32_t*)&h2;
            pk.w = *(const uint32_t*)&h3;
            *(uint4*)dst = pk;
        }
    }
}

// ---------------- pass 2: fp16 GEMM + fused LSTM epilogue ----------------
__global__ void __launch_bounds__(THREADS, 2)
lstm_mma_f16_kernel(Params p)
{
    extern __shared__ __align__(128) char smem[];
    const uint32_t sbase = smem_u32(smem);

    const int tid  = threadIdx.x;
    const int wid  = tid >> 5;
    const int lane = tid & 31;
    const int wm   = wid >> 1;        // 0..3 : rows wm*32
    const int wn   = wid & 1;         // 0..1 : j cols wn*16 per gate
    const int g4   = lane >> 2;
    const int t4   = lane & 3;

    const int bm = blockIdx.y * BM;
    const int j0 = blockIdx.x * BNG;

    // A: fragment-ordered gmem base for this warp (per chunk: +16384B; per mt: +2048; per kk: +512)
    const char* aBase = (const char*)(g_sA + (size_t)blockIdx.y * (32u * 8192u))
                        + wm * 4096 + lane * 16;
    const __half* tileB = g_sB + (size_t)blockIdx.x * (32u * 8192u);

    const uint32_t mb = sbase + MBAR_OFF;
    auto FULL = [&](int s) { return mb + (uint32_t)s * 8u; };
    uint32_t* cnt = (uint32_t*)(smem + CNT_OFF);

    if (tid == 0) {
        #pragma unroll
        for (int s = 0; s < NSTAGES; s++) { mbar_init(FULL(s), 1); cnt[s] = 0; }
    }
    __syncthreads();

    // ---- prologue: stage B chunks 0..3 ----
    if (tid == 0) {
        #pragma unroll
        for (int s = 0; s < NSTAGES; s++) {
            mbar_expect_tx(FULL(s), B_STAGE_BYTES);
            bulk_g2s(sbase + s * B_STAGE_BYTES, tileB + s * 8192, B_STAGE_BYTES, FULL(s));
        }
    }

    // ---- accumulators ----
    float acc[2][4][2][4];
    #pragma unroll
    for (int a = 0; a < 2; a++)
        #pragma unroll
        for (int b = 0; b < 4; b++)
            #pragma unroll
            for (int s = 0; s < 2; s++)
                #pragma unroll
                for (int q = 0; q < 4; q++) acc[a][b][s][q] = 0.0f;

    // ---- B ldsm addressing ----
    // row = g*32 + wn*16 + b_rsel; row&7 == lane&7 for all g.
    const int b_rsel = (lane & 7) + ((lane >> 4) << 3);
    const int b_ckad = ((lane >> 3) & 1);
    const int rx = lane & 7;
    uint32_t b_base[4];
    #pragma unroll
    for (int g = 0; g < 4; g++)
        b_base[g] = sbase + (uint32_t)((g * 32 + wn * 16 + b_rsel) * 128);

    // one pipeline step: chunk kt in stage S = kt&3; use = kt>>2.
    auto body = [&](auto Sc, int kt, bool do_stage) {
        constexpr int S = decltype(Sc)::value;
        constexpr uint32_t soff = (uint32_t)S * B_STAGE_BYTES;
        const uint32_t parity = (uint32_t)((kt >> 2) & 1);

        // A fragments: LDG.128 direct from fragment-ordered gmem, issued BEFORE
        // the B barrier wait so L2 latency hides behind it.
        uint4 av[2][4];
        const char* aC = aBase + kt * 16384;
        #pragma unroll
        for (int mt = 0; mt < 2; mt++)
            #pragma unroll
            for (int kk = 0; kk < 4; kk++)
                av[mt][kk] = __ldg((const uint4*)(aC + mt * 2048 + kk * 512));

        mbar_wait(FULL(S), parity);

        #pragma unroll
        for (int kk = 0; kk < 4; kk++) {
            uint32_t bfr[4][4];
            #pragma unroll
            for (int g = 0; g < 4; g++) {
                const int ck = kk * 2 + b_ckad;
                ldsm_x4(bfr[g], b_base[g] + soff + ((ck ^ rx) << 4));
            }
            #pragma unroll
            for (int mt = 0; mt < 2; mt++)
                #pragma unroll
                for (int g = 0; g < 4; g++) {
                    mma_f16(acc[mt][g][0], (const uint32_t*)&av[mt][kk], &bfr[g][0]);
                    mma_f16(acc[mt][g][1], (const uint32_t*)&av[mt][kk], &bfr[g][2]);
                }
        }

        if (do_stage && lane == 0) {
            const uint32_t old = atomicAdd(&cnt[S], 1u);
            if ((old & 7u) == 7u) {            // last reader -> stage chunk kt+4
                mbar_expect_tx(FULL(S), B_STAGE_BYTES);
                bulk_g2s(sbase + soff, tileB + (kt + 4) * 8192, B_STAGE_BYTES, FULL(S));
            }
        }
    };

    // ---- main loop: 32 chunks = 8 uses x 4 stages ----
    for (int use = 0; use < 7; use++) {
        body(IC<0>{}, use * 4 + 0, true);
        body(IC<1>{}, use * 4 + 1, true);
        body(IC<2>{}, use * 4 + 2, true);
        body(IC<3>{}, use * 4 + 3, true);
    }
    body(IC<0>{}, 28, false);
    body(IC<1>{}, 29, false);
    body(IC<2>{}, 30, false);
    body(IC<3>{}, 31, false);

    // ---- fused epilogue (register-resident) ----
    {
        float2 bb[4][2];
        #pragma unroll
        for (int g = 0; g < 4; g++)
            #pragma unroll
            for (int s2 = 0; s2 < 2; s2++)
                bb[g][s2] = *(const float2*)(p.bias[g] + j0 + wn * 16 + s2 * 8 + 2 * t4);

        #pragma unroll
        for (int mt = 0; mt < 2; mt++) {
            #pragma unroll
            for (int hh = 0; hh < 2; hh++) {
                const int row = bm + wm * 32 + mt * 16 + g4 + hh * 8;
                const size_t ro = (size_t)row * 1024 + j0 + wn * 16;
                #pragma unroll
                for (int s2 = 0; s2 < 2; s2++) {
                    const int co = s2 * 8 + 2 * t4;
                    const float2 cv = *(const float2*)(p.c + ro + co);
                    const int q = hh * 2;

                    const float i0 = sigm(acc[mt][0][s2][q]     + bb[0][s2].x);
                    const float i1 = sigm(acc[mt][0][s2][q + 1] + bb[0][s2].y);
                    const float f0 = sigm(acc[mt][1][s2][q]     + bb[1][s2].x);
                    const float f1 = sigm(acc[mt][1][s2][q + 1] + bb[1][s2].y);
                    const float o0 = sigm(acc[mt][2][s2][q]     + bb[2][s2].x);
                    const float o1 = sigm(acc[mt][2][s2][q + 1] + bb[2][s2].y);
                    const float c0 = ftanh(acc[mt][3][s2][q]     + bb[3][s2].x);
                    const float c1 = ftanh(acc[mt][3][s2][q + 1] + bb[3][s2].y);

                    const float nc0 = f0 * cv.x + i0 * c0;
                    const float nc1 = f1 * cv.y + i1 * c1;
                    float2 oh, oc;
                    oc.x = nc0; oc.y = nc1;
                    oh.x = o0 * ftanh(nc0);
                    oh.y = o1 * ftanh(nc1);
                    *(float2*)(p.outh + ro + co) = oh;
                    *(float2*)(p.outc + ro + co) = oc;
                }
            }
        }
    }
}

// ---------------- launch ----------------
extern "C" void kernel_launch(void* const* d_in, const int* in_sizes, int n_in,
                              void* d_out, int out_size)
{
    (void)in_sizes; (void)n_in; (void)out_size;

    Params p;
    p.x = (const float*)d_in[0];
    p.h = (const float*)d_in[1];
    p.c = (const float*)d_in[2];
    for (int g = 0; g < 4; g++) {   // (Wi,bi,Ui),(Wf,bf,Uf),(Wo,bo,Uo),(Wc,bc,Uc)
        p.W[g]    = (const float*)d_in[3 + 3 * g];
        p.bias[g] = (const float*)d_in[4 + 3 * g];
        p.U[g]    = (const float*)d_in[5 + 3 * g];
    }
    float* out = (float*)d_out;
    p.outh = out;
    p.outc = out + (size_t)BATCH * DH;

    static bool configured = false;
    if (!configured) {
        cudaFuncSetAttribute(lstm_mma_f16_kernel,
                             cudaFuncAttributeMaxDynamicSharedMemorySize, SMEM_BYTES);
        configured = true;
    }

    convert_kernel<<<A_BLOCKS + B_BLOCKS, 256>>>(p);

    dim3 grid(DH / BNG, BATCH / BM);   // (32, 64)
    lstm_mma_f16_kernel<<<grid, THREADS, SMEM_BYTES>>>(p);
}

// round 13
// speedup vs baseline: 1.0809x; 1.0809x over previous
#include <cuda_runtime.h>
#include <cuda_fp16.h>
#include <cstdint>

// ---------------- problem constants ----------------
constexpr int BATCH = 8192;
constexpr int DH    = 1024;

// ---------------- tiling ----------------
constexpr int BM      = 128;   // batch rows per CTA
constexpr int BNG     = 32;    // cols per gate per CTA
constexpr int NTOT    = 128;   // 4 gates x 32
constexpr int BK      = 64;    // K halfs per chunk (128B rows)
constexpr int KITERS  = 32;    // 2048 / 64
constexpr int THREADS = 256;   // 8 warps: 4(M) x 2(N)

constexpr int A_STAGE_BYTES = BM   * 128;                 // 16384
constexpr int B_STAGE_BYTES = NTOT * 128;                 // 16384
constexpr int STAGE_BYTES   = A_STAGE_BYTES + B_STAGE_BYTES;   // 32768
constexpr int MBAR_OFF      = 3 * STAGE_BYTES;                 // 98304 (3 FULL barriers)
constexpr int CNT_OFF       = MBAR_OFF + 32;                   // 3 u32 counters
constexpr int SMEM_BYTES    = MBAR_OFF + 64;                   // 98368 -> 2 CTAs/SM

// ---------------- scratch: pre-tiled + pre-swizzled fp16 ----------------
// A: [bt(64)][chunk(32)][128 rows x 128B, XOR-swizzled]  (chunks 0-15: x, 16-31: h)
// B: [jt(32)][chunk(32)][128 rows (g*32+jl) x 128B, XOR-swizzled]
__device__ __align__(128) __half g_sA[64u * 32u * 8192u];   // 32 MB
__device__ __align__(128) __half g_sB[32u * 32u * 8192u];   // 16 MB

template <int N> struct IC { static constexpr int value = N; };

struct Params {
    const float* x;
    const float* h;
    const float* c;
    const float* W[4];
    const float* U[4];
    const float* bias[4];
    float* outh;
    float* outc;
};

// ---------------- helpers ----------------
__device__ __forceinline__ uint32_t smem_u32(const void* p) {
    uint32_t a;
    asm("{ .reg .u64 t; cvta.to.shared.u64 t, %1; cvt.u32.u64 %0, t; }" : "=r"(a) : "l"(p));
    return a;
}
__device__ __forceinline__ void mbar_init(uint32_t a, uint32_t cnt) {
    asm volatile("mbarrier.init.shared.b64 [%0], %1;" :: "r"(a), "r"(cnt) : "memory");
}
__device__ __forceinline__ void mbar_expect_tx(uint32_t a, uint32_t tx) {
    asm volatile("mbarrier.arrive.expect_tx.shared.b64 _, [%0], %1;" :: "r"(a), "r"(tx) : "memory");
}
__device__ __forceinline__ void mbar_wait(uint32_t a, uint32_t parity) {
    asm volatile(
        "{\n\t.reg .pred P;\n"
        "W%=:\n\t"
        "mbarrier.try_wait.parity.shared::cta.b64 P, [%0], %1, 0x989680;\n\t"
        "@!P bra W%=;\n\t}"
        :: "r"(a), "r"(parity) : "memory");
}
__device__ __forceinline__ void bulk_g2s(uint32_t dst, const void* src, uint32_t bytes, uint32_t mbar) {
    asm volatile(
        "cp.async.bulk.shared::cluster.global.mbarrier::complete_tx::bytes [%0], [%1], %2, [%3];"
        :: "r"(dst), "l"(src), "r"(bytes), "r"(mbar) : "memory");
}
__device__ __forceinline__ void ldsm_x4(uint32_t* r, uint32_t addr) {
    asm volatile("ldmatrix.sync.aligned.m8n8.x4.shared.b16 {%0,%1,%2,%3}, [%4];"
        : "=r"(r[0]), "=r"(r[1]), "=r"(r[2]), "=r"(r[3]) : "r"(addr));
}
__device__ __forceinline__ void mma_f16(float* d, const uint32_t* a, const uint32_t* b) {
    asm volatile(
        "mma.sync.aligned.m16n8k16.row.col.f32.f16.f16.f32 "
        "{%0,%1,%2,%3}, {%4,%5,%6,%7}, {%8,%9}, {%0,%1,%2,%3};"
        : "+f"(d[0]), "+f"(d[1]), "+f"(d[2]), "+f"(d[3])
        : "r"(a[0]), "r"(a[1]), "r"(a[2]), "r"(a[3]), "r"(b[0]), "r"(b[1]));
}
__device__ __forceinline__ float sigm(float v) {
    return __fdividef(1.0f, 1.0f + __expf(-v));
}
__device__ __forceinline__ float ftanh(float v) {
    return __fmaf_rn(2.0f, sigm(2.0f * v), -1.0f);
}

// ---------------- pass 1: fp32 -> tiled/swizzled fp16 (512 thr, flat) ----------------
constexpr int ACH = 64 * 32 * 128 * 8;   // 2097152 16B-dst-chunks
constexpr int BCH = 32 * 32 * 128 * 8;   // 1048576
constexpr int TOTAL_CH = ACH + BCH;      // 3145728

__global__ void __launch_bounds__(512) convert_kernel(Params p)
{
    const int idx = blockIdx.x * 512 + threadIdx.x;
    if (idx >= TOTAL_CH) return;

    const float* src;
    __half* dst;
    if (idx < ACH) {
        const int c16 = idx & 7;
        const int r   = (idx >> 3) & 127;
        const int kc  = (idx >> 10) & 31;
        const int bt  = idx >> 15;
        src = (kc < 16 ? p.x : p.h)
              + (size_t)(bt * 128 + r) * 1024 + (kc & 15) * 64 + c16 * 8;
        dst = g_sA + ((size_t)(bt * 32 + kc) * 128 + r) * 64 + ((c16 ^ (r & 7)) * 8);
    } else {
        const int t   = idx - ACH;
        const int c16 = t & 7;
        const int r   = (t >> 3) & 127;        // g*32 + jl
        const int kc  = (t >> 10) & 31;
        const int jt  = t >> 15;
        const int g   = r >> 5, jl = r & 31;
        src = (kc < 16 ? p.W[g] : p.U[g])
              + (size_t)(jt * 32 + jl) * 1024 + (kc & 15) * 64 + c16 * 8;
        dst = g_sB + ((size_t)(jt * 32 + kc) * 128 + r) * 64 + ((c16 ^ (r & 7)) * 8);
    }
    const float4 v0 = *(const float4*)(src);
    const float4 v1 = *(const float4*)(src + 4);
    __half2 h0 = __floats2half2_rn(v0.x, v0.y);
    __half2 h1 = __floats2half2_rn(v0.z, v0.w);
    __half2 h2 = __floats2half2_rn(v1.x, v1.y);
    __half2 h3 = __floats2half2_rn(v1.z, v1.w);
    uint4 pk;
    pk.x = *(const uint32_t*)&h0;
    pk.y = *(const uint32_t*)&h1;
    pk.z = *(const uint32_t*)&h2;
    pk.w = *(const uint32_t*)&h3;
    *(uint4*)dst = pk;
}

// ---------------- pass 2: fp16 GEMM + fused LSTM epilogue ----------------
__global__ void __launch_bounds__(THREADS, 2)
lstm_mma_f16_kernel(Params p)
{
    extern __shared__ __align__(128) char smem[];
    const uint32_t sbase = smem_u32(smem);

    const int tid  = threadIdx.x;
    const int wid  = tid >> 5;
    const int lane = tid & 31;
    const int wm   = wid >> 1;        // 0..3 : rows wm*32
    const int wn   = wid & 1;         // 0..1 : j cols wn*16 per gate
    const int g4   = lane >> 2;
    const int t4   = lane & 3;

    const int bm = blockIdx.y * BM;
    const int j0 = blockIdx.x * BNG;

    const __half* tileA = g_sA + (size_t)blockIdx.y * (32u * 8192u);
    const __half* tileB = g_sB + (size_t)blockIdx.x * (32u * 8192u);

    const uint32_t mb = sbase + MBAR_OFF;
    auto FULL = [&](int s) { return mb + (uint32_t)s * 8u; };
    uint32_t* cnt = (uint32_t*)(smem + CNT_OFF);

    if (tid == 0) {
        #pragma unroll
        for (int s = 0; s < 3; s++) { mbar_init(FULL(s), 1); cnt[s] = 0; }
    }
    __syncthreads();

    // ---- prologue: stage chunks 0,1,2 ----
    if (tid == 0) {
        #pragma unroll
        for (int s = 0; s < 3; s++) {
            mbar_expect_tx(FULL(s), STAGE_BYTES);
            bulk_g2s(sbase + s * STAGE_BYTES,                 tileA + s * 8192, A_STAGE_BYTES, FULL(s));
            bulk_g2s(sbase + s * STAGE_BYTES + A_STAGE_BYTES, tileB + s * 8192, B_STAGE_BYTES, FULL(s));
        }
    }

    // ---- accumulators ----
    float acc[2][4][2][4];
    #pragma unroll
    for (int a = 0; a < 2; a++)
        #pragma unroll
        for (int b = 0; b < 4; b++)
            #pragma unroll
            for (int s = 0; s < 2; s++)
                #pragma unroll
                for (int q = 0; q < 4; q++) acc[a][b][s][q] = 0.0f;

    // ---- per-lane ldmatrix row/col selection ----
    const int a_rsel = (lane & 7) + (((lane >> 3) & 1) << 3);
    const int a_ckad = (lane >> 4);
    const int b_rsel = (lane & 7) + ((lane >> 4) << 3);
    const int b_ckad = ((lane >> 3) & 1);

    uint32_t a_base[2]; int a_rx[2];
    #pragma unroll
    for (int mt = 0; mt < 2; mt++) {
        const int row = wm * 32 + mt * 16 + a_rsel;
        a_base[mt] = sbase + (uint32_t)(row * 128);
        a_rx[mt]   = row & 7;
    }
    uint32_t b_base[4]; int b_rx[4];
    #pragma unroll
    for (int g = 0; g < 4; g++) {
        const int row = g * 32 + wn * 16 + b_rsel;
        b_base[g] = sbase + (uint32_t)(A_STAGE_BYTES + row * 128);
        b_rx[g]   = row & 7;
    }

    // one pipeline step: chunk kt lives in buffer S; use index = kt/3.
    // End-of-chunk: each warp's lane0 bumps cnt[S] (after its MMAs have issued,
    // so its ldsm reads are physically complete). The warp observing the 8th
    // increment of this use is the LAST reader and immediately stages chunk kt+3.
    auto body = [&](auto Sc, int kt, int use, bool do_stage) {
        constexpr int S = decltype(Sc)::value;
        constexpr uint32_t soff = (uint32_t)S * STAGE_BYTES;
        const uint32_t parity = (uint32_t)(use & 1);

        mbar_wait(FULL(S), parity);

        #pragma unroll
        for (int kk = 0; kk < 4; kk++) {
            uint32_t afr[2][4];
            #pragma unroll
            for (int mt = 0; mt < 2; mt++) {
                const int ck = kk * 2 + a_ckad;
                ldsm_x4(afr[mt], a_base[mt] + soff + ((ck ^ a_rx[mt]) << 4));
            }
            uint32_t bfr[4][4];
            #pragma unroll
            for (int g = 0; g < 4; g++) {
                const int ck = kk * 2 + b_ckad;
                ldsm_x4(bfr[g], b_base[g] + soff + ((ck ^ b_rx[g]) << 4));
            }
            #pragma unroll
            for (int mt = 0; mt < 2; mt++)
                #pragma unroll
                for (int g = 0; g < 4; g++) {
                    mma_f16(acc[mt][g][0], afr[mt], &bfr[g][0]);
                    mma_f16(acc[mt][g][1], afr[mt], &bfr[g][2]);
                }
        }

        if (do_stage && lane == 0) {
            const uint32_t old = atomicAdd(&cnt[S], 1u);
            if ((old & 7u) == 7u) {            // last reader of this use -> stage
                const int kn = kt + 3;
                mbar_expect_tx(FULL(S), STAGE_BYTES);
                bulk_g2s(sbase + soff,                 tileA + kn * 8192, A_STAGE_BYTES, FULL(S));
                bulk_g2s(sbase + soff + A_STAGE_BYTES, tileB + kn * 8192, B_STAGE_BYTES, FULL(S));
            }
        }
    };

    // ---- main loop: 32 chunks = 10 x 3 + 2 (staging stops at chunk 31) ----
    for (int use = 0; use < 9; use++) {
        body(IC<0>{}, use * 3 + 0, use, true);
        body(IC<1>{}, use * 3 + 1, use, true);
        body(IC<2>{}, use * 3 + 2, use, true);
    }
    body(IC<0>{}, 27, 9, true);
    body(IC<1>{}, 28, 9, true);
    body(IC<2>{}, 29, 9, false);
    body(IC<0>{}, 30, 10, false);
    body(IC<1>{}, 31, 10, false);

    // ---- fused epilogue (register-resident) ----
    {
        float2 bb[4][2];
        #pragma unroll
        for (int g = 0; g < 4; g++)
            #pragma unroll
            for (int s2 = 0; s2 < 2; s2++)
                bb[g][s2] = *(const float2*)(p.bias[g] + j0 + wn * 16 + s2 * 8 + 2 * t4);

        #pragma unroll
        for (int mt = 0; mt < 2; mt++) {
            #pragma unroll
            for (int hh = 0; hh < 2; hh++) {
                const int row = bm + wm * 32 + mt * 16 + g4 + hh * 8;
                const size_t ro = (size_t)row * 1024 + j0 + wn * 16;
                #pragma unroll
                for (int s2 = 0; s2 < 2; s2++) {
                    const int co = s2 * 8 + 2 * t4;
                    const float2 cv = *(const float2*)(p.c + ro + co);
                    const int q = hh * 2;

                    const float i0 = sigm(acc[mt][0][s2][q]     + bb[0][s2].x);
                    const float i1 = sigm(acc[mt][0][s2][q + 1] + bb[0][s2].y);
                    const float f0 = sigm(acc[mt][1][s2][q]     + bb[1][s2].x);
                    const float f1 = sigm(acc[mt][1][s2][q + 1] + bb[1][s2].y);
                    const float o0 = sigm(acc[mt][2][s2][q]     + bb[2][s2].x);
                    const float o1 = sigm(acc[mt][2][s2][q + 1] + bb[2][s2].y);
                    const float c0 = ftanh(acc[mt][3][s2][q]     + bb[3][s2].x);
                    const float c1 = ftanh(acc[mt][3][s2][q + 1] + bb[3][s2].y);

                    const float nc0 = f0 * cv.x + i0 * c0;
                    const float nc1 = f1 * cv.y + i1 * c1;
                    float2 oh, oc;
                    oc.x = nc0; oc.y = nc1;
                    oh.x = o0 * ftanh(nc0);
                    oh.y = o1 * ftanh(nc1);
                    *(float2*)(p.outh + ro + co) = oh;
                    *(float2*)(p.outc + ro + co) = oc;
                }
            }
        }
    }
}

// ---------------- launch ----------------
extern "C" void kernel_launch(void* const* d_in, const int* in_sizes, int n_in,
                              void* d_out, int out_size)
{
    (void)in_sizes; (void)n_in; (void)out_size;

    Params p;
    p.x = (const float*)d_in[0];
    p.h = (const float*)d_in[1];
    p.c = (const float*)d_in[2];
    for (int g = 0; g < 4; g++) {   // (Wi,bi,Ui),(Wf,bf,Uf),(Wo,bo,Uo),(Wc,bc,Uc)
        p.W[g]    = (const float*)d_in[3 + 3 * g];
        p.bias[g] = (const float*)d_in[4 + 3 * g];
        p.U[g]    = (const float*)d_in[5 + 3 * g];
    }
    float* out = (float*)d_out;
    p.outh = out;
    p.outc = out + (size_t)BATCH * DH;

    static bool configured = false;
    if (!configured) {
        cudaFuncSetAttribute(lstm_mma_f16_kernel,
                             cudaFuncAttributeMaxDynamicSharedMemorySize, SMEM_BYTES);
        configured = true;
    }

    convert_kernel<<<(TOTAL_CH + 511) / 512, 512>>>(p);

    dim3 grid(DH / BNG, BATCH / BM);   // (32, 64)
    lstm_mma_f16_kernel<<<grid, THREADS, SMEM_BYTES>>>(p);
}